// round 2
// baseline (speedup 1.0000x reference)
#include <cuda_runtime.h>
#include <cstdint>

#define NN 8192
#define PP 49
#define FF 256
#define EE 256
#define HH 256
#define SS 128
#define MTOT (NN * PP)  // 401408

// Scratch (no allocations allowed)
__device__ float g_x2[NN * EE];     // 8 MB
__device__ float g_scores[NN];
__device__ float g_attn[NN];

__device__ __forceinline__ unsigned f2tf32(float f) {
    unsigned r;
    asm("cvt.rna.tf32.f32 %0, %1;" : "=r"(r) : "f"(f));
    return r;
}

// ---------------------------------------------------------------------------
// K1: x2[n,e] = tanh(hidden[n,:] . W2[e,:] + b2[e]).  fp32, 64x64 tiles.
// Also zeroes g_scores (512 blocks * 16 = 8192).
// ---------------------------------------------------------------------------
__global__ __launch_bounds__(256) void k1_x2(const float* __restrict__ Hm,
                                             const float* __restrict__ W2,
                                             const float* __restrict__ b2) {
    __shared__ float As[64][17];
    __shared__ float Bs[64][17];
    int tid = threadIdx.x;
    int tx = tid & 15, ty = tid >> 4;
    int nb = blockIdx.y * 64, eb = blockIdx.x * 64;

    int bid = blockIdx.y * gridDim.x + blockIdx.x;  // 0..511
    if (tid < 16) g_scores[bid * 16 + tid] = 0.f;

    float acc[4][4] = {};
    for (int k0 = 0; k0 < HH; k0 += 16) {
        int r = tid >> 2, c4 = tid & 3;
        float4 va = *(const float4*)&Hm[(size_t)(nb + r) * HH + k0 + c4 * 4];
        float4 vb = *(const float4*)&W2[(size_t)(eb + r) * HH + k0 + c4 * 4];
        As[r][c4 * 4 + 0] = va.x; As[r][c4 * 4 + 1] = va.y;
        As[r][c4 * 4 + 2] = va.z; As[r][c4 * 4 + 3] = va.w;
        Bs[r][c4 * 4 + 0] = vb.x; Bs[r][c4 * 4 + 1] = vb.y;
        Bs[r][c4 * 4 + 2] = vb.z; Bs[r][c4 * 4 + 3] = vb.w;
        __syncthreads();
#pragma unroll
        for (int kk = 0; kk < 16; kk++) {
            float ra[4], rb[4];
#pragma unroll
            for (int i = 0; i < 4; i++) ra[i] = As[ty * 4 + i][kk];
#pragma unroll
            for (int j = 0; j < 4; j++) rb[j] = Bs[tx * 4 + j][kk];
#pragma unroll
            for (int i = 0; i < 4; i++)
#pragma unroll
                for (int j = 0; j < 4; j++) acc[i][j] += ra[i] * rb[j];
        }
        __syncthreads();
    }
#pragma unroll
    for (int i = 0; i < 4; i++)
#pragma unroll
        for (int j = 0; j < 4; j++) {
            int n = nb + ty * 4 + i, e = eb + tx * 4 + j;
            g_x2[(size_t)n * EE + e] = tanhf(acc[i][j] + b2[e]);
        }
}

// ---------------------------------------------------------------------------
// K2: the big one. Per CTA: rows [mb*256, +256) of flattened (n,p), one
// 128-wide e-half.  tf32 mma.sync m16n8k8, fp32 accum.  Epilogue applies
// b1 + tanh, dots with x2[n,:], reduces each row to a scalar and
// atomically accumulates scores[n] += rowdot / 49.
// ---------------------------------------------------------------------------
__global__ __launch_bounds__(256, 1) void k2_scores(const float* __restrict__ X,
                                                    const float* __restrict__ W1,
                                                    const float* __restrict__ b1) {
    __shared__ __align__(16) float xs[256 * 24];   // 24 KB
    __shared__ __align__(16) float ws[128 * 24];   // 12 KB
    __shared__ float x2s[8][128];                  // 4 KB
    __shared__ float b1s[128];

    int tid = threadIdx.x;
    int w = tid >> 5, lane = tid & 31, g = lane >> 2, tig = lane & 3;
    int mb = blockIdx.x;
    int eh = blockIdx.y;
    int row0 = mb * 256;
    int e0 = eh * 128;
    int n_base = row0 / PP;

    // preload x2 slice (rows span <= 7 distinct n) and b1 half
    for (int i = tid; i < 8 * 128; i += 256) {
        int nn = n_base + (i >> 7);
        x2s[i >> 7][i & 127] = (nn < NN) ? g_x2[(size_t)nn * EE + e0 + (i & 127)] : 0.f;
    }
    if (tid < 128) b1s[tid] = b1[e0 + tid];

    float acc[2][16][4];
#pragma unroll
    for (int mt = 0; mt < 2; mt++)
#pragma unroll
        for (int nt = 0; nt < 16; nt++)
#pragma unroll
            for (int i = 0; i < 4; i++) acc[mt][nt][i] = 0.f;

    for (int k0 = 0; k0 < FF; k0 += 16) {
        // xs: 256 rows x 16 k (1024 float4, 4/thread), permuted pair layout
#pragma unroll
        for (int i = 0; i < 4; i++) {
            int idx = tid + i * 256;
            int r = idx >> 2, c4 = idx & 3;
            float4 v = *(const float4*)&X[(size_t)(row0 + r) * FF + k0 + c4 * 4];
            int base = r * 24 + ((c4 >> 1) << 3) + (c4 & 1);
            xs[base + 0] = __uint_as_float(f2tf32(v.x));
            xs[base + 2] = __uint_as_float(f2tf32(v.y));
            xs[base + 4] = __uint_as_float(f2tf32(v.z));
            xs[base + 6] = __uint_as_float(f2tf32(v.w));
        }
        // ws: 128 e-rows x 16 k (512 float4, 2/thread)
#pragma unroll
        for (int i = 0; i < 2; i++) {
            int idx = tid + i * 256;
            int r = idx >> 2, c4 = idx & 3;
            float4 v = *(const float4*)&W1[(size_t)(e0 + r) * FF + k0 + c4 * 4];
            int base = r * 24 + ((c4 >> 1) << 3) + (c4 & 1);
            ws[base + 0] = __uint_as_float(f2tf32(v.x));
            ws[base + 2] = __uint_as_float(f2tf32(v.y));
            ws[base + 4] = __uint_as_float(f2tf32(v.z));
            ws[base + 6] = __uint_as_float(f2tf32(v.w));
        }
        __syncthreads();
#pragma unroll
        for (int ks = 0; ks < 2; ks++) {
            uint2 A[2][2];
#pragma unroll
            for (int mt = 0; mt < 2; mt++) {
                int ra = w * 32 + mt * 16 + g;
                A[mt][0] = *(const uint2*)&xs[ra * 24 + ks * 8 + tig * 2];
                A[mt][1] = *(const uint2*)&xs[(ra + 8) * 24 + ks * 8 + tig * 2];
            }
#pragma unroll
            for (int nt = 0; nt < 16; nt++) {
                uint2 B = *(const uint2*)&ws[(nt * 8 + g) * 24 + ks * 8 + tig * 2];
#pragma unroll
                for (int mt = 0; mt < 2; mt++) {
                    asm volatile(
                        "mma.sync.aligned.m16n8k8.row.col.f32.tf32.tf32.f32 "
                        "{%0,%1,%2,%3}, {%4,%5,%6,%7}, {%8,%9}, {%0,%1,%2,%3};\n"
                        : "+f"(acc[mt][nt][0]), "+f"(acc[mt][nt][1]),
                          "+f"(acc[mt][nt][2]), "+f"(acc[mt][nt][3])
                        : "r"(A[mt][0].x), "r"(A[mt][1].x),
                          "r"(A[mt][0].y), "r"(A[mt][1].y),
                          "r"(B.x), "r"(B.y));
                }
            }
        }
        __syncthreads();
    }

    // epilogue: tanh(acc + b1) . x2[n] per row, reduce over quad, atomicAdd
    const float inv = 1.f / (float)PP;
#pragma unroll
    for (int mt = 0; mt < 2; mt++) {
        int rA = w * 32 + mt * 16 + g;
        int rB = rA + 8;
        int nA = (row0 + rA) / PP, nB = (row0 + rB) / PP;
        const float* xA = x2s[nA - n_base];
        const float* xB = x2s[nB - n_base];
        float sA = 0.f, sB = 0.f;
#pragma unroll
        for (int nt = 0; nt < 16; nt++) {
            int c0 = nt * 8 + tig * 2, c1 = c0 + 1;
            sA += tanhf(acc[mt][nt][0] + b1s[c0]) * xA[c0]
                + tanhf(acc[mt][nt][1] + b1s[c1]) * xA[c1];
            sB += tanhf(acc[mt][nt][2] + b1s[c0]) * xB[c0]
                + tanhf(acc[mt][nt][3] + b1s[c1]) * xB[c1];
        }
        sA += __shfl_xor_sync(0xffffffffu, sA, 1);
        sA += __shfl_xor_sync(0xffffffffu, sA, 2);
        sB += __shfl_xor_sync(0xffffffffu, sB, 1);
        sB += __shfl_xor_sync(0xffffffffu, sB, 2);
        if (tig == 0) {
            atomicAdd(&g_scores[nA], sA * inv);
            atomicAdd(&g_scores[nB], sB * inv);
        }
    }
}

// ---------------------------------------------------------------------------
// K3: per-segment softmax over scalar scores. One block per segment.
// patch_lens may be int32 or int64 depending on whether the reference ran
// with JAX x64 enabled. Values are in [33,95] (never 0), so little-endian
// detection via p32[1]==0 is robust: int64 -> (lo,0) word pairs.
// ---------------------------------------------------------------------------
__device__ __forceinline__ int seg_len(const int* p32, int is64, int i) {
    return is64 ? p32[2 * i] : p32[i];
}

__global__ __launch_bounds__(128) void k3_softmax(const int* __restrict__ lens32) {
    __shared__ float sh[128];
    __shared__ int s_off, s_len;
    int s = blockIdx.x, tid = threadIdx.x;
    if (tid == 0) {
        int is64 = (lens32[1] == 0) ? 1 : 0;
        int o = 0;
        for (int i = 0; i < s; i++) o += seg_len(lens32, is64, i);
        s_off = o;
        s_len = seg_len(lens32, is64, s);
    }
    __syncthreads();
    int off = s_off, len = s_len;
    float v = (tid < len) ? g_scores[off + tid] : -1e30f;
    sh[tid] = v;
    __syncthreads();
    for (int st = 64; st > 0; st >>= 1) {
        if (tid < st) sh[tid] = fmaxf(sh[tid], sh[tid + st]);
        __syncthreads();
    }
    float m = sh[0];
    __syncthreads();
    float e = (tid < len) ? expf(v - m) : 0.f;
    sh[tid] = e;
    __syncthreads();
    for (int st = 64; st > 0; st >>= 1) {
        if (tid < st) sh[tid] += sh[tid + st];
        __syncthreads();
    }
    float z = sh[0];
    if (tid < len) g_attn[off + tid] = e / z;
}

// ---------------------------------------------------------------------------
// K4: out[n,f] = attn[n] * sum_p x[n,p,f]
// ---------------------------------------------------------------------------
__global__ __launch_bounds__(256) void k4_out(const float* __restrict__ X,
                                              float* __restrict__ out) {
    int n = blockIdx.x, f = threadIdx.x;
    const float* xp = X + (size_t)n * PP * FF + f;
    float acc = 0.f;
#pragma unroll
    for (int p = 0; p < PP; p++) acc += xp[(size_t)p * FF];
    out[(size_t)n * FF + f] = acc * g_attn[n];
}

// ---------------------------------------------------------------------------
extern "C" void kernel_launch(void* const* d_in, const int* in_sizes, int n_in,
                              void* d_out, int out_size) {
    const float* x      = (const float*)d_in[0];  // [8192,49,256]
    const float* hidden = (const float*)d_in[1];  // [1,8192,256]
    const float* W1     = (const float*)d_in[2];  // [256,256]
    const float* b1     = (const float*)d_in[3];  // [256]
    const float* W2     = (const float*)d_in[4];  // [256,256]
    const float* b2     = (const float*)d_in[5];  // [256]
    const int* pl       = (const int*)d_in[6];    // [128] int32 or int64

    float* out = (float*)d_out;

    k1_x2<<<dim3(4, 128), 256>>>(hidden, W2, b2);
    k2_scores<<<dim3(MTOT / 256, 2), 256>>>(x, W1, b1);
    k3_softmax<<<SS, 128>>>(pl);
    k4_out<<<NN, 256>>>(x, out);
}

// round 4
// speedup vs baseline: 1.4846x; 1.4846x over previous
#include <cuda_runtime.h>
#include <cuda_fp16.h>
#include <cstdint>

#define NN 8192
#define PP 49
#define FF 256
#define EE 256
#define HH 256
#define SS 128
#define MTOT (NN * PP)  // 401408

// Scratch (no allocations allowed)
__device__ float  g_x2[NN * EE];     // 8 MB
__device__ __half g_w1h[EE * FF];    // 128 KB, fp16 W1 [e][k]
__device__ float  g_scores[NN];
__device__ float  g_attn[NN];

// ---------------------------------------------------------------------------
// helpers
// ---------------------------------------------------------------------------
__device__ __forceinline__ uint32_t smem_u32(const void* p) {
    uint32_t a;
    asm("{ .reg .u64 t; cvta.to.shared.u64 t, %1; cvt.u32.u64 %0, t; }" : "=r"(a) : "l"(p));
    return a;
}
// accurate-enough fast tanh for k1 (err ~1e-6)
__device__ __forceinline__ float ftanh(float x) {
    float e = __expf(2.f * x);
    return 1.f - __fdividef(2.f, e + 1.f);
}
// hardware tanh (1 MUFU, abs err ~5e-4) for the bulk epilogue
__device__ __forceinline__ float tanha(float x) {
    float y;
    asm("tanh.approx.f32 %0, %1;" : "=f"(y) : "f"(x));
    return y;
}

#define LDSM4(r, addr) \
    asm volatile("ldmatrix.sync.aligned.m8n8.x4.shared.b16 {%0,%1,%2,%3}, [%4];" \
        : "=r"((r)[0]), "=r"((r)[1]), "=r"((r)[2]), "=r"((r)[3]) : "r"(addr))

#define MMA16816(c, a, b0v, b1v) \
    asm volatile("mma.sync.aligned.m16n8k16.row.col.f32.f16.f16.f32 " \
        "{%0,%1,%2,%3},{%4,%5,%6,%7},{%8,%9},{%0,%1,%2,%3};" \
        : "+f"((c)[0]), "+f"((c)[1]), "+f"((c)[2]), "+f"((c)[3]) \
        : "r"((a)[0]), "r"((a)[1]), "r"((a)[2]), "r"((a)[3]), "r"(b0v), "r"(b1v))

__device__ __forceinline__ uint32_t pack_h2(float a, float b) {
    __half2 h = __floats2half2_rn(a, b);
    return *(uint32_t*)&h;
}

// ---------------------------------------------------------------------------
// K1: x2[n,e] = tanh(hidden . W2^T + b2).  fp32 SIMT, 64x64 tiles.
// Also zeroes g_scores and converts W1 -> g_w1h (fp16).
// ---------------------------------------------------------------------------
__global__ __launch_bounds__(256) void k1_x2(const float* __restrict__ Hm,
                                             const float* __restrict__ W2,
                                             const float* __restrict__ b2,
                                             const float* __restrict__ W1) {
    __shared__ float As[64][17];
    __shared__ float Bs[64][17];
    int tid = threadIdx.x;
    int tx = tid & 15, ty = tid >> 4;
    int nb = blockIdx.y * 64, eb = blockIdx.x * 64;

    int bid = blockIdx.y * gridDim.x + blockIdx.x;  // 0..511
    if (tid < 16) g_scores[bid * 16 + tid] = 0.f;
    // W1 -> fp16 (65536 elems / 512 blocks = 128 per block)
    if (tid < 128) {
        int i = bid * 128 + tid;
        g_w1h[i] = __float2half_rn(W1[i]);
    }

    float acc[4][4] = {};
    for (int k0 = 0; k0 < HH; k0 += 16) {
        int r = tid >> 2, c4 = tid & 3;
        float4 va = *(const float4*)&Hm[(size_t)(nb + r) * HH + k0 + c4 * 4];
        float4 vb = *(const float4*)&W2[(size_t)(eb + r) * HH + k0 + c4 * 4];
        As[r][c4 * 4 + 0] = va.x; As[r][c4 * 4 + 1] = va.y;
        As[r][c4 * 4 + 2] = va.z; As[r][c4 * 4 + 3] = va.w;
        Bs[r][c4 * 4 + 0] = vb.x; Bs[r][c4 * 4 + 1] = vb.y;
        Bs[r][c4 * 4 + 2] = vb.z; Bs[r][c4 * 4 + 3] = vb.w;
        __syncthreads();
#pragma unroll
        for (int kk = 0; kk < 16; kk++) {
            float ra[4], rb[4];
#pragma unroll
            for (int i = 0; i < 4; i++) ra[i] = As[ty * 4 + i][kk];
#pragma unroll
            for (int j = 0; j < 4; j++) rb[j] = Bs[tx * 4 + j][kk];
#pragma unroll
            for (int i = 0; i < 4; i++)
#pragma unroll
                for (int j = 0; j < 4; j++) acc[i][j] += ra[i] * rb[j];
        }
        __syncthreads();
    }
#pragma unroll
    for (int i = 0; i < 4; i++)
#pragma unroll
        for (int j = 0; j < 4; j++) {
            int n = nb + ty * 4 + i, e = eb + tx * 4 + j;
            g_x2[(size_t)n * EE + e] = ftanh(acc[i][j] + b2[e]);
        }
}

// ---------------------------------------------------------------------------
// K2: scores via fp16 mma.sync m16n8k16.
// CTA = 128 rows x 256 e, K = 256.  W1 (fp16) persistent in SMEM (528B-stride
// padded, conflict-free for ldmatrix).  A double-buffered (80B stride),
// register-prefetched, 1 sync/chunk.  8 warps: 2 (m) x 4 (n), warp tile 64x64.
// Epilogue: tanh.approx + dot(x2) + quad shuffle + atomicAdd.
// ---------------------------------------------------------------------------
#define OFF_B1  0        // 1024 B
#define OFF_X2  1024     // 4*260*4 = 4160 -> ends 5184
#define OFF_BW  5248     // 256*528 = 135168 -> ends 140416
#define OFF_A   140416   // 2 * 128*80 = 20480 -> ends 160896
#define A_BUF   10240
#define K2_SMEM 160896

__global__ __launch_bounds__(256, 1) void k2_scores(const float* __restrict__ X,
                                                    const float* __restrict__ b1) {
    extern __shared__ __align__(16) char smem[];
    float* b1s = (float*)(smem + OFF_B1);
    float* x2s = (float*)(smem + OFF_X2);

    const int tid = threadIdx.x;
    const int w = tid >> 5, lane = tid & 31;
    const int tig = lane & 3, g = lane >> 2;
    const int wm = w >> 2, wn = w & 3;          // warp grid 2(m) x 4(n)
    const int row0 = blockIdx.x * 128;
    const int n0 = row0 / PP;

    // ---- prefetch A chunk 0 (this thread's 16 consecutive k-floats) ----
    const float* Xp = X + (size_t)(row0 + (tid >> 1)) * FF + (tid & 1) * 16;
    float4 pr0 = *(const float4*)(Xp + 0);
    float4 pr1 = *(const float4*)(Xp + 4);
    float4 pr2 = *(const float4*)(Xp + 8);
    float4 pr3 = *(const float4*)(Xp + 12);

    // ---- B preload: g_w1h (128KB) -> padded smem rows (528B stride) ----
    {
        const uint4* Wp = (const uint4*)g_w1h;
        for (int i = tid; i < 8192; i += 256) {
            int r = i >> 5, s2 = i & 31;
            *(uint4*)(smem + OFF_BW + r * 528 + s2 * 16) = Wp[i];
        }
    }
    // ---- x2 slice (<=4 distinct n) + b1 ----
    for (int i = tid; i < 4 * EE; i += 256) {
        int s = i >> 8, e = i & 255;
        int n = n0 + s;
        x2s[s * 260 + e] = (n < NN) ? g_x2[(size_t)n * EE + e] : 0.f;
    }
    if (tid < EE) b1s[tid] = b1[tid];

    float acc[4][8][4];
#pragma unroll
    for (int mt = 0; mt < 4; mt++)
#pragma unroll
        for (int nt = 0; nt < 8; nt++)
#pragma unroll
            for (int i = 0; i < 4; i++) acc[mt][nt][i] = 0.f;

    const uint32_t sb = smem_u32(smem);
    // ldmatrix lane addressing
    const int arow = lane & 15, asel = lane >> 4;
    const uint32_t aAddr0 = sb + OFF_A + (uint32_t)(wm * 64 + arow) * 80 + asel * 16;
    const int brow = (lane & 7) + ((lane >> 4) << 3), bsel = (lane >> 3) & 1;
    const uint32_t bAddr0 = sb + OFF_BW + (uint32_t)(wn * 64 + brow) * 528 + bsel * 16;
    // STS addressing for A
    char* stsP = smem + OFF_A + (tid >> 1) * 80 + (tid & 1) * 32;

    for (int kc = 0; kc < 8; kc++) {
        const int buf = kc & 1;
        const uint32_t bo = buf * A_BUF;
        // store prefetched A chunk (fp32 -> fp16)
        {
            uint4 q0, q1;
            q0.x = pack_h2(pr0.x, pr0.y); q0.y = pack_h2(pr0.z, pr0.w);
            q0.z = pack_h2(pr1.x, pr1.y); q0.w = pack_h2(pr1.z, pr1.w);
            q1.x = pack_h2(pr2.x, pr2.y); q1.y = pack_h2(pr2.z, pr2.w);
            q1.z = pack_h2(pr3.x, pr3.y); q1.w = pack_h2(pr3.z, pr3.w);
            *(uint4*)(stsP + bo) = q0;
            *(uint4*)(stsP + bo + 16) = q1;
        }
        __syncthreads();
        // prefetch next chunk
        if (kc < 7) {
            const float* Xn = Xp + (kc + 1) * 32;
            pr0 = *(const float4*)(Xn + 0);
            pr1 = *(const float4*)(Xn + 4);
            pr2 = *(const float4*)(Xn + 8);
            pr3 = *(const float4*)(Xn + 12);
        }
        // compute: 2 x k16 steps
#pragma unroll
        for (int ks = 0; ks < 2; ks++) {
            uint32_t Ar[4][4], Br[4][4];
#pragma unroll
            for (int mt = 0; mt < 4; mt++)
                LDSM4(Ar[mt], aAddr0 + bo + mt * (16 * 80) + ks * 32);
#pragma unroll
            for (int np = 0; np < 4; np++)
                LDSM4(Br[np], bAddr0 + np * (16 * 528) + kc * 64 + ks * 32);
#pragma unroll
            for (int mt = 0; mt < 4; mt++)
#pragma unroll
                for (int nt = 0; nt < 8; nt++)
                    MMA16816(acc[mt][nt], Ar[mt], Br[nt >> 1][(nt & 1) * 2],
                             Br[nt >> 1][(nt & 1) * 2 + 1]);
        }
        // single sync per iter is safe: per-warp order STS(buf)->sync->MMA(buf)
    }

    // ---- epilogue ----
    const float inv = 1.f / (float)PP;
    const float* b1w = b1s + wn * 64;
#pragma unroll
    for (int mt = 0; mt < 4; mt++) {
        int rA = wm * 64 + mt * 16 + g;      // CTA-local rows
        int rB = rA + 8;
        int nA = (row0 + rA) / PP;
        int nB = (row0 + rB) / PP;
        const float* xA = x2s + (nA - n0) * 260 + wn * 64;
        const float* xB = x2s + (nB - n0) * 260 + wn * 64;
        float sA = 0.f, sB = 0.f;
#pragma unroll
        for (int nt = 0; nt < 8; nt++) {
            int c0 = nt * 8 + tig * 2, c1 = c0 + 1;
            sA += tanha(acc[mt][nt][0] + b1w[c0]) * xA[c0]
                + tanha(acc[mt][nt][1] + b1w[c1]) * xA[c1];
            sB += tanha(acc[mt][nt][2] + b1w[c0]) * xB[c0]
                + tanha(acc[mt][nt][3] + b1w[c1]) * xB[c1];
        }
        sA += __shfl_xor_sync(0xffffffffu, sA, 1);
        sA += __shfl_xor_sync(0xffffffffu, sA, 2);
        sB += __shfl_xor_sync(0xffffffffu, sB, 1);
        sB += __shfl_xor_sync(0xffffffffu, sB, 2);
        if (tig == 0) {
            atomicAdd(&g_scores[nA], sA * inv);
            atomicAdd(&g_scores[nB], sB * inv);
        }
    }
}

// ---------------------------------------------------------------------------
// K3: per-segment softmax over scalar scores. patch_lens may be int32 or
// int64 (values in [33,95], never 0 -> LE detect via word1==0).
// ---------------------------------------------------------------------------
__device__ __forceinline__ int seg_len(const int* p32, int is64, int i) {
    return is64 ? p32[2 * i] : p32[i];
}

__global__ __launch_bounds__(128) void k3_softmax(const int* __restrict__ lens32) {
    __shared__ float sh[128];
    __shared__ int s_off, s_len;
    int s = blockIdx.x, tid = threadIdx.x;
    if (tid == 0) {
        int is64 = (lens32[1] == 0) ? 1 : 0;
        int o = 0;
        for (int i = 0; i < s; i++) o += seg_len(lens32, is64, i);
        s_off = o;
        s_len = seg_len(lens32, is64, s);
    }
    __syncthreads();
    int off = s_off, len = s_len;
    float v = (tid < len) ? g_scores[off + tid] : -1e30f;
    sh[tid] = v;
    __syncthreads();
    for (int st = 64; st > 0; st >>= 1) {
        if (tid < st) sh[tid] = fmaxf(sh[tid], sh[tid + st]);
        __syncthreads();
    }
    float m = sh[0];
    __syncthreads();
    float e = (tid < len) ? expf(v - m) : 0.f;
    sh[tid] = e;
    __syncthreads();
    for (int st = 64; st > 0; st >>= 1) {
        if (tid < st) sh[tid] += sh[tid + st];
        __syncthreads();
    }
    float z = sh[0];
    if (tid < len) g_attn[off + tid] = e / z;
}

// ---------------------------------------------------------------------------
// K4: out[n,f] = attn[n] * sum_p x[n,p,f]   (DRAM-bound, ~83% of peak)
// ---------------------------------------------------------------------------
__global__ __launch_bounds__(256) void k4_out(const float* __restrict__ X,
                                              float* __restrict__ out) {
    int n = blockIdx.x, f = threadIdx.x;
    const float* xp = X + (size_t)n * PP * FF + f;
    float acc = 0.f;
#pragma unroll
    for (int p = 0; p < PP; p++) acc += xp[(size_t)p * FF];
    out[(size_t)n * FF + f] = acc * g_attn[n];
}

// ---------------------------------------------------------------------------
extern "C" void kernel_launch(void* const* d_in, const int* in_sizes, int n_in,
                              void* d_out, int out_size) {
    const float* x      = (const float*)d_in[0];  // [8192,49,256]
    const float* hidden = (const float*)d_in[1];  // [1,8192,256]
    const float* W1     = (const float*)d_in[2];  // [256,256]
    const float* b1     = (const float*)d_in[3];  // [256]
    const float* W2     = (const float*)d_in[4];  // [256,256]
    const float* b2     = (const float*)d_in[5];  // [256]
    const int* pl       = (const int*)d_in[6];    // [128] int32 or int64

    float* out = (float*)d_out;

    static int attr_set = 0;
    if (!attr_set) {
        cudaFuncSetAttribute(k2_scores, cudaFuncAttributeMaxDynamicSharedMemorySize, K2_SMEM);
        attr_set = 1;
    }

    k1_x2<<<dim3(4, 128), 256>>>(hidden, W2, b2, W1);
    k2_scores<<<MTOT / 128, 256, K2_SMEM>>>(x, b1);
    k3_softmax<<<SS, 128>>>(pl);
    k4_out<<<NN, 256>>>(x, out);
}